// round 3
// baseline (speedup 1.0000x reference)
#include <cuda_runtime.h>
#include <math_constants.h>

#define D 1024
#define NKEYS 32768
#define TOPK 10
#define NBLOCKS 1024
#define QBLOCKS 256          // blocks doing qproj (4 q-rows each) — must be wave-1 resident

// Scratch (device globals — no allocations allowed)
__device__ float g_q[D];
__device__ float g_scores[NKEYS];
__device__ float g_bmax[NBLOCKS];
__device__ int   g_bidx[NBLOCKS];
__device__ float g_zpart[NBLOCKS];
__device__ unsigned g_cnt1 = 0;   // qproj done counter
__device__ unsigned g_cnt2 = 0;   // scores done counter

__global__ void __launch_bounds__(256, 2) fused_kernel(
    const float* __restrict__ query,
    const float* __restrict__ keys,
    const float* __restrict__ values,
    const float* __restrict__ Wq,
    const float* __restrict__ bq,
    float* __restrict__ out)
{
    const int tid  = threadIdx.x;
    const int warp = tid >> 5, lane = tid & 31;
    const int bid  = blockIdx.x;
    const float inv = 0.03125f;               // 1/sqrt(1024)

    __shared__ float4 qs[D / 4];
    __shared__ float  sc[32];
    __shared__ float  qpart[8];

    // ---- prefetch first half of my keys tile into L2 (overlaps qproj) ----
    {
        const char* base = (const char*)(keys + (size_t)bid * 32 * D);
        // 16 rows * 4KB = 64KB = 512 lines of 128B, 2 per thread
#pragma unroll
        for (int j = 0; j < 2; j++) {
            const char* p = base + (size_t)(tid + 256 * j) * 128;
            asm volatile("prefetch.global.L2 [%0];" :: "l"(p));
        }
    }

    // ---- phase 1: qproj on blocks 0..QBLOCKS-1 (4 rows, 2 warps per row) ----
    if (bid < QBLOCKS) {
        int row  = bid * 4 + (warp >> 1);
        int half = warp & 1;                  // half-row = 128 float4
        const float4* wp = (const float4*)(Wq + (size_t)row * D) + half * 128;
        const float4* qv = (const float4*)query + half * 128;
        float acc = 0.f;
#pragma unroll
        for (int j = 0; j < 4; j++) {
            float4 a = wp[lane + 32 * j];
            float4 b = qv[lane + 32 * j];
            acc += a.x * b.x + a.y * b.y + a.z * b.z + a.w * b.w;
        }
#pragma unroll
        for (int o = 16; o; o >>= 1) acc += __shfl_down_sync(~0u, acc, o);
        if (lane == 0) qpart[warp] = acc;
        __syncthreads();
        if (warp == 0 && lane < 4) {
            int r = bid * 4 + lane;
            g_q[r] = qpart[lane * 2] + qpart[lane * 2 + 1] + bq[r];
        }
        __threadfence();
        __syncthreads();
        if (tid == 0) atomicAdd(&g_cnt1, 1u);
    }

    // ---- wait for q (only wave-1-resident blocks 0..255 are required) ----
    if (tid == 0) {
        volatile unsigned* c = &g_cnt1;
        while (*c < QBLOCKS) __nanosleep(64);
    }
    __syncthreads();
    __threadfence();

    qs[tid] = ((const float4*)g_q)[tid];
    __syncthreads();

    // ---- phase 2: 32 score rows per block (warp handles 4) ----
    int rowBase = bid * 32 + warp * 4;
#pragma unroll
    for (int r = 0; r < 4; r++) {
        int row = rowBase + r;
        const float4* kp = (const float4*)(keys + (size_t)row * D);
        float acc = 0.f;
#pragma unroll
        for (int j = 0; j < 8; j++) {
            float4 a = kp[lane + 32 * j];
            float4 b = qs[lane + 32 * j];
            acc += a.x * b.x + a.y * b.y + a.z * b.z + a.w * b.w;
        }
#pragma unroll
        for (int o = 16; o; o >>= 1) acc += __shfl_down_sync(~0u, acc, o);
        if (lane == 0) { g_scores[row] = acc; sc[warp * 4 + r] = acc; }
    }
    __syncthreads();

    // block stats: exp-sum partial, max + argmax over the 32 scores
    if (warp == 0) {
        float v = sc[lane];
        int   i = bid * 32 + lane;
        float z = expf(v * inv);
#pragma unroll
        for (int o = 16; o; o >>= 1) z += __shfl_down_sync(~0u, z, o);
        float mv = v; int mi = i;
#pragma unroll
        for (int o = 16; o; o >>= 1) {
            float ov = __shfl_down_sync(~0u, mv, o);
            int   oi = __shfl_down_sync(~0u, mi, o);
            if (ov > mv || (ov == mv && oi < mi)) { mv = ov; mi = oi; }
        }
        if (lane == 0) {
            g_zpart[bid] = z;
            g_bmax[bid]  = mv;
            g_bidx[bid]  = mi;
        }
    }
    __threadfence();
    __syncthreads();

    __shared__ unsigned sLast;
    if (tid == 0) sLast = atomicAdd(&g_cnt2, 1u);
    __syncthreads();
    if (sLast != NBLOCKS - 1) return;

    // ================= tail: elected last block (256 threads) =================
    __threadfence();

    __shared__ float tbm[NBLOCKS];
    __shared__ int   tbi[NBLOCKS];
    __shared__ float zw[8];
    __shared__ float sZ;
    __shared__ int   chosenIdx[TOPK];
    __shared__ float chosenVal[TOPK];
    __shared__ int   sWinBlk;

    // Z = sum of 1024 partials (fixed-order tree -> deterministic)
    {
        float z = 0.f;
#pragma unroll
        for (int j = 0; j < 4; j++) z += g_zpart[tid * 4 + j];
#pragma unroll
        for (int o = 16; o; o >>= 1) z += __shfl_down_sync(~0u, z, o);
        if (lane == 0) zw[warp] = z;
        __syncthreads();
        if (tid == 0) {
            float s = 0.f;
#pragma unroll
            for (int j = 0; j < 8; j++) s += zw[j];
            sZ = s;
        }
    }

    // load block maxima
#pragma unroll
    for (int j = 0; j < 4; j++) {
        int b = tid + 256 * j;
        tbm[b] = g_bmax[b];
        tbi[b] = g_bidx[b];
    }
    __syncthreads();

    __shared__ float wv[8];
    __shared__ int   wi[8];

    for (int r = 0; r < TOPK; r++) {
        // argmax over 1024 block maxima
        float mv = -CUDART_INF_F; int mi = 0x7FFFFFFF;
#pragma unroll
        for (int j = 0; j < 4; j++) {
            int b = tid + 256 * j;
            float v = tbm[b];
            int   i = tbi[b];
            if (v > mv || (v == mv && i < mi)) { mv = v; mi = i; }
        }
#pragma unroll
        for (int o = 16; o; o >>= 1) {
            float ov = __shfl_down_sync(~0u, mv, o);
            int   oi = __shfl_down_sync(~0u, mi, o);
            if (ov > mv || (ov == mv && oi < mi)) { mv = ov; mi = oi; }
        }
        if (lane == 0) { wv[warp] = mv; wi[warp] = mi; }
        __syncthreads();
        if (tid == 0) {
            float bv = wv[0]; int bi2 = wi[0];
#pragma unroll
            for (int j = 1; j < 8; j++) {
                if (wv[j] > bv || (wv[j] == bv && wi[j] < bi2)) { bv = wv[j]; bi2 = wi[j]; }
            }
            chosenIdx[r] = bi2;
            chosenVal[r] = bv;
            sWinBlk = bi2 >> 5;
        }
        __syncthreads();

        // warp 0 rescans the winning 32-element group, excluding chosen
        if (warp == 0) {
            int b = sWinBlk;
            int e = b * 32 + lane;
            float v = g_scores[e];
#pragma unroll
            for (int t = 0; t < TOPK; t++) {
                if (t <= r && chosenIdx[t] == e) v = -CUDART_INF_F;
            }
            float m2 = v; int i2 = e;
#pragma unroll
            for (int o = 16; o; o >>= 1) {
                float ov = __shfl_down_sync(~0u, m2, o);
                int   oi = __shfl_down_sync(~0u, i2, o);
                if (ov > m2 || (ov == m2 && oi < i2)) { m2 = ov; i2 = oi; }
            }
            if (lane == 0) { tbm[b] = m2; tbi[b] = i2; }
        }
        __syncthreads();
    }

    // gather the 10 value rows (2560 float4, 256 threads)
#pragma unroll
    for (int f = tid; f < TOPK * (D / 4); f += 256) {
        int r = f >> 8;
        int c = f & 255;
        ((float4*)(out + (size_t)r * D))[c] =
            ((const float4*)(values + (size_t)chosenIdx[r] * D))[c];
    }
    if (tid < TOPK) {
        out[TOPK * D + tid] = expf(chosenVal[tid] * inv) / sZ;
    }

    // reset counters for the next graph replay.
    // Safe: cnt2 == NBLOCKS means every block already passed both spins.
    __threadfence();
    if (tid == 0) { g_cnt1 = 0; g_cnt2 = 0; }
}

// ---------------------------------------------------------------------------
extern "C" void kernel_launch(void* const* d_in, const int* in_sizes, int n_in,
                              void* d_out, int out_size) {
    const float* query  = (const float*)d_in[0];
    const float* keys   = (const float*)d_in[1];
    const float* values = (const float*)d_in[2];
    const float* Wq     = (const float*)d_in[3];
    const float* bq     = (const float*)d_in[4];
    float* out = (float*)d_out;

    fused_kernel<<<NBLOCKS, 256>>>(query, keys, values, Wq, bq, out);
}

// round 6
// speedup vs baseline: 1.1376x; 1.1376x over previous
#include <cuda_runtime.h>
#include <math_constants.h>

#define D 1024
#define NKEYS 32768
#define TOPK 10
#define NBLOCKS 1024

// Scratch (device globals — no allocations allowed)
__device__ float g_q[D];
__device__ float g_scores[NKEYS];
__device__ float g_bmax[NBLOCKS];
__device__ int   g_bidx[NBLOCKS];
__device__ float g_zpart[NBLOCKS];

// ---------------------------------------------------------------------------
// Kernel 1: q = Wq @ query + bq.  256 blocks x 256 thr.
// Block owns 4 rows; each row split across 2 warps (half-row each).
// ---------------------------------------------------------------------------
__global__ void __launch_bounds__(256) qproj_kernel(const float* __restrict__ Wq,
                                                    const float* __restrict__ query,
                                                    const float* __restrict__ bq) {
    __shared__ float qpart[8];
    const int tid = threadIdx.x;
    const int warp = tid >> 5, lane = tid & 31;

    const int row  = blockIdx.x * 4 + (warp >> 1);
    const int half = warp & 1;                 // 128 float4 per half-row
    const float4* wp = (const float4*)(Wq + (size_t)row * D) + half * 128;
    const float4* qv = (const float4*)query + half * 128;
    float acc = 0.f;
#pragma unroll
    for (int j = 0; j < 4; j++) {
        float4 a = wp[lane + 32 * j];
        float4 b = qv[lane + 32 * j];
        acc += a.x * b.x + a.y * b.y + a.z * b.z + a.w * b.w;
    }
#pragma unroll
    for (int o = 16; o; o >>= 1) acc += __shfl_down_sync(~0u, acc, o);
    if (lane == 0) qpart[warp] = acc;
    __syncthreads();
    if (warp == 0 && lane < 4) {
        const int r = blockIdx.x * 4 + lane;
        g_q[r] = qpart[lane * 2] + qpart[lane * 2 + 1] + bq[r];
    }
}

// ---------------------------------------------------------------------------
// Kernel 2: scores = keys @ q  +  per-block stats (z-partial, max, argmax).
// 1024 blocks x 256 thr; each warp 4 rows with interleaved accumulators
// (32 independent float4 loads in flight per warp).
// ---------------------------------------------------------------------------
__global__ void __launch_bounds__(256) scores_kernel(const float* __restrict__ keys) {
    __shared__ float4 qs[D / 4];
    __shared__ float  sc[32];
    const int tid = threadIdx.x;
    const int warp = tid >> 5, lane = tid & 31;
    const int bid = blockIdx.x;
    const float inv = 0.03125f;                // 1/sqrt(1024)

    qs[tid] = ((const float4*)g_q)[tid];
    __syncthreads();

    const int row0 = bid * 32 + warp * 4;
    const float4* kp = (const float4*)(keys + (size_t)row0 * D);   // 4 rows = 1024 float4
    float a0 = 0.f, a1 = 0.f, a2 = 0.f, a3 = 0.f;
#pragma unroll
    for (int j = 0; j < 8; j++) {
        const float4 b  = qs[lane + 32 * j];
        const float4 v0 = kp[lane + 32 * j];
        const float4 v1 = kp[lane + 32 * j + 256];
        const float4 v2 = kp[lane + 32 * j + 512];
        const float4 v3 = kp[lane + 32 * j + 768];
        a0 += v0.x * b.x + v0.y * b.y + v0.z * b.z + v0.w * b.w;
        a1 += v1.x * b.x + v1.y * b.y + v1.z * b.z + v1.w * b.w;
        a2 += v2.x * b.x + v2.y * b.y + v2.z * b.z + v2.w * b.w;
        a3 += v3.x * b.x + v3.y * b.y + v3.z * b.z + v3.w * b.w;
    }
#pragma unroll
    for (int o = 16; o; o >>= 1) {
        a0 += __shfl_down_sync(~0u, a0, o);
        a1 += __shfl_down_sync(~0u, a1, o);
        a2 += __shfl_down_sync(~0u, a2, o);
        a3 += __shfl_down_sync(~0u, a3, o);
    }
    if (lane == 0) {
        g_scores[row0 + 0] = a0;  sc[warp * 4 + 0] = a0;
        g_scores[row0 + 1] = a1;  sc[warp * 4 + 1] = a1;
        g_scores[row0 + 2] = a2;  sc[warp * 4 + 2] = a2;
        g_scores[row0 + 3] = a3;  sc[warp * 4 + 3] = a3;
    }
    __syncthreads();

    // warp 0: block stats over the 32 scores
    if (warp == 0) {
        const float v = sc[lane];
        const int   i = bid * 32 + lane;
        float z = expf(v * inv);
#pragma unroll
        for (int o = 16; o; o >>= 1) z += __shfl_down_sync(~0u, z, o);
        float mv = v; int mi = i;
#pragma unroll
        for (int o = 16; o; o >>= 1) {
            const float ov = __shfl_down_sync(~0u, mv, o);
            const int   oi = __shfl_down_sync(~0u, mi, o);
            if (ov > mv || (ov == mv && oi < mi)) { mv = ov; mi = oi; }
        }
        if (lane == 0) {
            g_zpart[bid] = z;
            g_bmax[bid]  = mv;
            g_bidx[bid]  = mi;
        }
    }
}

// ---------------------------------------------------------------------------
// Kernel 3: tail — Z reduce, top-10 over 1024 block maxima (winner-group
// rescan from L2-resident g_scores), gather, weights. 1 block x 256 thr.
// Output: [retrieved_values (10*1024 f32), top_w (10 f32)]
// ---------------------------------------------------------------------------
__global__ void __launch_bounds__(256) tail_kernel(const float* __restrict__ values,
                                                   float* __restrict__ out) {
    __shared__ float tbm[NBLOCKS];
    __shared__ int   tbi[NBLOCKS];
    __shared__ float zw[8];
    __shared__ float sZ;
    __shared__ int   chosenIdx[TOPK];
    __shared__ float chosenVal[TOPK];
    __shared__ int   sWinBlk;
    __shared__ float wv[8];
    __shared__ int   wi[8];

    const int tid = threadIdx.x;
    const int warp = tid >> 5, lane = tid & 31;
    const float inv = 0.03125f;

    // Z = sum of 1024 partials (fixed order -> deterministic)
    {
        float z = 0.f;
#pragma unroll
        for (int j = 0; j < 4; j++) z += g_zpart[tid * 4 + j];
#pragma unroll
        for (int o = 16; o; o >>= 1) z += __shfl_down_sync(~0u, z, o);
        if (lane == 0) zw[warp] = z;
    }
    // load block maxima into smem
#pragma unroll
    for (int j = 0; j < 4; j++) {
        const int b = tid + 256 * j;
        tbm[b] = g_bmax[b];
        tbi[b] = g_bidx[b];
    }
    __syncthreads();
    if (tid == 0) {
        float s = 0.f;
#pragma unroll
        for (int j = 0; j < 8; j++) s += zw[j];
        sZ = s;
    }
    __syncthreads();

    for (int r = 0; r < TOPK; r++) {
        float mv = -CUDART_INF_F; int mi = 0x7FFFFFFF;
#pragma unroll
        for (int j = 0; j < 4; j++) {
            const int b = tid + 256 * j;
            const float v = tbm[b];
            const int   i = tbi[b];
            if (v > mv || (v == mv && i < mi)) { mv = v; mi = i; }
        }
#pragma unroll
        for (int o = 16; o; o >>= 1) {
            const float ov = __shfl_down_sync(~0u, mv, o);
            const int   oi = __shfl_down_sync(~0u, mi, o);
            if (ov > mv || (ov == mv && oi < mi)) { mv = ov; mi = oi; }
        }
        if (lane == 0) { wv[warp] = mv; wi[warp] = mi; }
        __syncthreads();
        if (tid == 0) {
            float bv = wv[0]; int bi = wi[0];
#pragma unroll
            for (int j = 1; j < 8; j++) {
                if (wv[j] > bv || (wv[j] == bv && wi[j] < bi)) { bv = wv[j]; bi = wi[j]; }
            }
            chosenIdx[r] = bi;
            chosenVal[r] = bv;
            sWinBlk = bi >> 5;
        }
        __syncthreads();

        // warp 0 rescans the winning block's 32 scores, excluding chosen ones
        if (warp == 0) {
            const int b = sWinBlk;
            const int e = b * 32 + lane;
            float v = g_scores[e];
#pragma unroll
            for (int t = 0; t < TOPK; t++) {
                if (t <= r && chosenIdx[t] == e) v = -CUDART_INF_F;
            }
            float m2 = v; int i2 = e;
#pragma unroll
            for (int o = 16; o; o >>= 1) {
                const float ov = __shfl_down_sync(~0u, m2, o);
                const int   oi = __shfl_down_sync(~0u, i2, o);
                if (ov > m2 || (ov == m2 && oi < i2)) { m2 = ov; i2 = oi; }
            }
            if (lane == 0) { tbm[b] = m2; tbi[b] = i2; }
        }
        __syncthreads();
    }

    // gather the 10 value rows (2560 float4, 256 threads)
#pragma unroll
    for (int f = tid; f < TOPK * (D / 4); f += 256) {
        const int r = f >> 8;
        const int c = f & 255;
        ((float4*)(out + (size_t)r * D))[c] =
            ((const float4*)(values + (size_t)chosenIdx[r] * D))[c];
    }
    if (tid < TOPK) {
        out[TOPK * D + tid] = expf(chosenVal[tid] * inv) / sZ;
    }
}

// ---------------------------------------------------------------------------
extern "C" void kernel_launch(void* const* d_in, const int* in_sizes, int n_in,
                              void* d_out, int out_size) {
    const float* query  = (const float*)d_in[0];
    const float* keys   = (const float*)d_in[1];
    const float* values = (const float*)d_in[2];
    const float* Wq     = (const float*)d_in[3];
    const float* bq     = (const float*)d_in[4];
    float* out = (float*)d_out;

    qproj_kernel<<<256, 256>>>(Wq, query, bq);
    scores_kernel<<<NBLOCKS, 256>>>(keys);
    tail_kernel<<<1, 256>>>(values, out);
}